// round 1
// baseline (speedup 1.0000x reference)
#include <cuda_runtime.h>
#include <cuda_bf16.h>
#include <cstddef>

// Problem constants
#define BB    8
#define NN    1024
#define DD    512
#define HH    8
#define HD    64
#define FFD   2048
#define LL    6
#define CC    5
#define DIN   64
#define MTOT  (BB*NN)   // 8192

// ---------------- static scratch (no allocations allowed) ----------------
__device__ float g_x [MTOT*DD];
__device__ float g_q [MTOT*DD];
__device__ float g_k [MTOT*DD];
__device__ float g_v [MTOT*DD];
__device__ float g_t [MTOT*DD];
__device__ float g_ff[MTOT*FFD];

// ---------------- TN SGEMM: C[M,N] = A[M,K] @ B[N,K]^T + bias, opt ReLU ----
// 128x128 tile, BK=8, 256 threads, 8x8 microtile.
__global__ void __launch_bounds__(256) gemm_tn(
    int M, int N, int K,
    const float* __restrict__ A, int lda,
    const float* __restrict__ B, int ldb,
    const float* __restrict__ bias,
    float* __restrict__ C, int ldc, int relu)
{
    __shared__ float As[8][128];
    __shared__ float Bs[8][128];

    int tid = threadIdx.x;
    int tx = tid & 15, ty = tid >> 4;
    int row0 = blockIdx.y << 7, col0 = blockIdx.x << 7;

    float acc[8][8];
#pragma unroll
    for (int i = 0; i < 8; i++)
#pragma unroll
        for (int j = 0; j < 8; j++) acc[i][j] = 0.f;

    // each thread loads one float4 of A and one of B per K-tile
    int r  = tid >> 1;            // 0..127
    int c0 = (tid & 1) << 2;      // 0 or 4
    bool arow_ok = (row0 + r) < M;
    bool brow_ok = (col0 + r) < N;
    const float* Ap = A + (size_t)(row0 + r) * lda + c0;
    const float* Bp = B + (size_t)(col0 + r) * ldb + c0;

    for (int k0 = 0; k0 < K; k0 += 8) {
        float4 va = arow_ok ? *(const float4*)(Ap + k0) : make_float4(0.f,0.f,0.f,0.f);
        float4 vb = brow_ok ? *(const float4*)(Bp + k0) : make_float4(0.f,0.f,0.f,0.f);
        As[c0+0][r] = va.x; As[c0+1][r] = va.y; As[c0+2][r] = va.z; As[c0+3][r] = va.w;
        Bs[c0+0][r] = vb.x; Bs[c0+1][r] = vb.y; Bs[c0+2][r] = vb.z; Bs[c0+3][r] = vb.w;
        __syncthreads();
#pragma unroll
        for (int kk = 0; kk < 8; kk++) {
            float a[8], b[8];
#pragma unroll
            for (int i = 0; i < 8; i++) { a[i] = As[kk][ty + 16*i]; b[i] = Bs[kk][tx + 16*i]; }
#pragma unroll
            for (int i = 0; i < 8; i++)
#pragma unroll
                for (int j = 0; j < 8; j++) acc[i][j] += a[i] * b[j];
        }
        __syncthreads();
    }

#pragma unroll
    for (int i = 0; i < 8; i++) {
        int rr = row0 + ty + 16*i;
        if (rr >= M) continue;
#pragma unroll
        for (int j = 0; j < 8; j++) {
            int cc = col0 + tx + 16*j;
            if (cc >= N) continue;
            float v = acc[i][j] + (bias ? bias[cc] : 0.f);
            if (relu) v = fmaxf(v, 0.f);
            C[(size_t)rr * ldc + cc] = v;
        }
    }
}

// ---------------- fused flash attention (fp32) ----------------
// block: 128 threads handles one (b, h, 32-query tile). Streams K/V in
// 32-key tiles with online softmax; O accumulated in registers.
// thread t: qr = t/4 (query row), kq = t%4.
//   S-phase: owns keys kq*8 .. kq*8+7
//   O-phase: owns dims d = kq + 4*j, j=0..15 (interleaved -> conflict-free LDS)
__global__ void __launch_bounds__(128) attn_fused(
    const float* __restrict__ Q, const float* __restrict__ K,
    const float* __restrict__ V, const unsigned char* __restrict__ kpm,
    float* __restrict__ O)
{
    __shared__ float Qs[32][65];
    __shared__ float Ks[32][65];
    __shared__ float Vs[32][64];
    __shared__ float Ps[32][33];

    int b = blockIdx.z, h = blockIdx.y, q0 = blockIdx.x << 5;
    int t = threadIdx.x;
    int qr = t >> 2, kq = t & 3, kb = kq << 3;

    // load Q tile
    for (int idx = t; idx < 32*64; idx += 128) {
        int rr = idx >> 6, dd = idx & 63;
        Qs[rr][dd] = Q[((size_t)(b*NN + q0 + rr)) * DD + h*HD + dd];
    }

    float Oa[16];
#pragma unroll
    for (int j = 0; j < 16; j++) Oa[j] = 0.f;
    float mprev = -1e30f, l = 0.f;

    for (int kt = 0; kt < NN/32; kt++) {
        __syncthreads();  // previous O-phase done reading Vs/Ps
        for (int idx = t; idx < 32*64; idx += 128) {
            int rr = idx >> 6, dd = idx & 63;
            size_t gi = ((size_t)(b*NN + kt*32 + rr)) * DD + h*HD + dd;
            Ks[rr][dd] = K[gi];
            Vs[rr][dd] = V[gi];
        }
        __syncthreads();

        // S = Q K^T (scaled, masked)
        float s[8];
#pragma unroll
        for (int j = 0; j < 8; j++) s[j] = 0.f;
#pragma unroll 4
        for (int d = 0; d < 64; d++) {
            float qv = Qs[qr][d];
#pragma unroll
            for (int j = 0; j < 8; j++) s[j] += qv * Ks[kb + j][d];
        }
        float mloc = -1e30f;
#pragma unroll
        for (int j = 0; j < 8; j++) {
            int key = kt*32 + kb + j;
            s[j] *= 0.125f;                       // 1/sqrt(64)
            if (kpm[b*NN + key]) s[j] = -1e30f;
            mloc = fmaxf(mloc, s[j]);
        }
        mloc = fmaxf(mloc, __shfl_xor_sync(0xffffffffu, mloc, 1));
        mloc = fmaxf(mloc, __shfl_xor_sync(0xffffffffu, mloc, 2));
        float mnew = fmaxf(mprev, mloc);
        float corr = __expf(mprev - mnew);

        float ps = 0.f;
#pragma unroll
        for (int j = 0; j < 8; j++) {
            float p = __expf(s[j] - mnew);
            Ps[qr][kb + j] = p;
            ps += p;
        }
        ps += __shfl_xor_sync(0xffffffffu, ps, 1);
        ps += __shfl_xor_sync(0xffffffffu, ps, 2);
        l = l * corr + ps;
#pragma unroll
        for (int j = 0; j < 16; j++) Oa[j] *= corr;
        mprev = mnew;
        __syncwarp();  // Ps written within quad (same warp)

        // O += P V  (thread's dims: kq + 4*j)
#pragma unroll 4
        for (int key = 0; key < 32; key++) {
            float p = Ps[qr][key];
#pragma unroll
            for (int j = 0; j < 16; j++) Oa[j] += p * Vs[key][kq + 4*j];
        }
    }

    float inv = (l > 0.f) ? (1.f / l) : 0.f;
    size_t base = ((size_t)(b*NN + q0 + qr)) * DD + h*HD;
#pragma unroll
    for (int j = 0; j < 16; j++) O[base + kq + 4*j] = Oa[j] * inv;
}

// ---------------- residual add + LayerNorm (in-place capable) ----------------
__global__ void __launch_bounds__(128) ln_kernel(
    const float* __restrict__ x, const float* __restrict__ res,
    const float* __restrict__ g, const float* __restrict__ bparam,
    float* __restrict__ out)
{
    int row = blockIdx.x, t = threadIdx.x;
    const float* xr = x + (size_t)row * DD;
    const float* rr = res ? res + (size_t)row * DD : nullptr;
    float v[4];
#pragma unroll
    for (int i = 0; i < 4; i++) {
        int d = t + 128*i;
        v[i] = xr[d] + (rr ? rr[d] : 0.f);
    }
    float s = v[0] + v[1] + v[2] + v[3];
#pragma unroll
    for (int o = 16; o > 0; o >>= 1) s += __shfl_xor_sync(0xffffffffu, s, o);
    __shared__ float sh[4];
    if ((t & 31) == 0) sh[t >> 5] = s;
    __syncthreads();
    float mu = (sh[0] + sh[1] + sh[2] + sh[3]) * (1.f / DD);
    __syncthreads();
    float q2 = 0.f;
#pragma unroll
    for (int i = 0; i < 4; i++) { float d = v[i] - mu; q2 += d * d; }
#pragma unroll
    for (int o = 16; o > 0; o >>= 1) q2 += __shfl_xor_sync(0xffffffffu, q2, o);
    if ((t & 31) == 0) sh[t >> 5] = q2;
    __syncthreads();
    float var = (sh[0] + sh[1] + sh[2] + sh[3]) * (1.f / DD);
    float rs = rsqrtf(var + 1e-5f);
#pragma unroll
    for (int i = 0; i < 4; i++) {
        int d = t + 128*i;
        out[(size_t)row * DD + d] = (v[i] - mu) * rs * g[d] + bparam[d];
    }
}

// ---------------- launch ----------------
extern "C" void kernel_launch(void* const* d_in, const int* in_sizes, int n_in,
                              void* d_out, int out_size)
{
    const float* src      = (const float*)d_in[0];
    const unsigned char* kpm = (const unsigned char*)d_in[1];
    const float* embed_W  = (const float*)d_in[2];
    const float* embed_b  = (const float*)d_in[3];
    const float* Wq = (const float*)d_in[4];
    const float* bq = (const float*)d_in[5];
    const float* Wk = (const float*)d_in[6];
    const float* bk = (const float*)d_in[7];
    const float* Wv = (const float*)d_in[8];
    const float* bv = (const float*)d_in[9];
    const float* Wo = (const float*)d_in[10];
    const float* bo = (const float*)d_in[11];
    const float* W1 = (const float*)d_in[12];
    const float* b1 = (const float*)d_in[13];
    const float* W2 = (const float*)d_in[14];
    const float* b2 = (const float*)d_in[15];
    const float* ln1_g = (const float*)d_in[16];
    const float* ln1_b = (const float*)d_in[17];
    const float* ln2_g = (const float*)d_in[18];
    const float* ln2_b = (const float*)d_in[19];
    const float* fin_g = (const float*)d_in[20];
    const float* fin_b = (const float*)d_in[21];
    const float* head_W = (const float*)d_in[22];
    const float* head_b = (const float*)d_in[23];

    float *x, *q, *k, *v, *t, *ff;
    cudaGetSymbolAddress((void**)&x,  g_x);
    cudaGetSymbolAddress((void**)&q,  g_q);
    cudaGetSymbolAddress((void**)&k,  g_k);
    cudaGetSymbolAddress((void**)&v,  g_v);
    cudaGetSymbolAddress((void**)&t,  g_t);
    cudaGetSymbolAddress((void**)&ff, g_ff);

    dim3 gD(DD/128, MTOT/128);     // 4 x 64
    dim3 gF(FFD/128, MTOT/128);    // 16 x 64
    dim3 gH(1, MTOT/128);
    dim3 gA(NN/32, HH, BB);        // 32 x 8 x 8

    // embed: x = src @ embed_W^T + embed_b
    gemm_tn<<<gD, 256>>>(MTOT, DD, DIN, src, DIN, embed_W, DIN, embed_b, x, DD, 0);

    for (int l = 0; l < LL; l++) {
        const float* Wq_l = Wq + (size_t)l*DD*DD;
        const float* Wk_l = Wk + (size_t)l*DD*DD;
        const float* Wv_l = Wv + (size_t)l*DD*DD;
        const float* Wo_l = Wo + (size_t)l*DD*DD;
        const float* W1_l = W1 + (size_t)l*FFD*DD;
        const float* W2_l = W2 + (size_t)l*DD*FFD;

        gemm_tn<<<gD, 256>>>(MTOT, DD, DD, x, DD, Wq_l, DD, bq + l*DD, q, DD, 0);
        gemm_tn<<<gD, 256>>>(MTOT, DD, DD, x, DD, Wk_l, DD, bk + l*DD, k, DD, 0);
        gemm_tn<<<gD, 256>>>(MTOT, DD, DD, x, DD, Wv_l, DD, bv + l*DD, v, DD, 0);

        attn_fused<<<gA, 128>>>(q, k, v, kpm, t);

        gemm_tn<<<gD, 256>>>(MTOT, DD, DD, t, DD, Wo_l, DD, bo + l*DD, q, DD, 0);
        ln_kernel<<<MTOT, 128>>>(x, q, ln1_g + l*DD, ln1_b + l*DD, x);

        gemm_tn<<<gF, 256>>>(MTOT, FFD, DD, x, DD, W1_l, DD, b1 + l*FFD, ff, FFD, 1);
        gemm_tn<<<gD, 256>>>(MTOT, DD, FFD, ff, FFD, W2_l, FFD, b2 + l*DD, t, DD, 0);
        ln_kernel<<<MTOT, 128>>>(x, t, ln2_g + l*DD, ln2_b + l*DD, x);
    }

    ln_kernel<<<MTOT, 128>>>(x, nullptr, fin_g, fin_b, x);
    gemm_tn<<<gH, 256>>>(MTOT, CC, DD, x, DD, head_W, DD, head_b, (float*)d_out, CC, 0);
}